// round 4
// baseline (speedup 1.0000x reference)
#include <cuda_runtime.h>
#include <cstdint>

#define N_NODES 50000
#define N_EDGES 800000
#define DIN     369
#define D       128
#define D3      384
#define TT      13
#define STEPS   8
#define NG      256

// ---------------- scratch (static device allocations only) ----------------
__device__ float d_H[TT * N_NODES * D];        // per-type hidden state (333 MB)
__device__ float d_S[TT * N_NODES * D];        // per-type scatter accumulator (333 MB)
__device__ float d_Q[TT * STEPS * D * D3];     // W[t,s] @ w_ih[t]^T   (20.4 MB)
__device__ float d_R[TT * D * D3];             // w_hh[t]^T            (2.6 MB)
__device__ int   d_esrc[N_EDGES];              // t*N + src  (type-bucketed)
__device__ int   d_edst[N_EDGES];              // t*N + dst
__device__ int   d_counts[TT];
__device__ int   d_offsets[TT + 1];
__device__ int   d_cursor[TT];
__device__ float d_pool[NG * D];
__device__ float d_cnt[NG];

// ---------------- helpers ----------------
__device__ __forceinline__ void fma2(unsigned long long& d,
                                     unsigned long long a,
                                     unsigned long long b) {
    asm("fma.rn.f32x2 %0, %1, %2, %0;" : "+l"(d) : "l"(a), "l"(b));
}
__device__ __forceinline__ unsigned long long dup2(float v) {
    unsigned int u = __float_as_uint(v);
    return ((unsigned long long)u << 32) | u;
}
__device__ __forceinline__ unsigned long long pack2(float lo, float hi) {
    return ((unsigned long long)__float_as_uint(hi) << 32) | __float_as_uint(lo);
}
__device__ __forceinline__ float2 u2f2(unsigned long long u) {
    float2 f;
    f.x = __uint_as_float((unsigned int)u);
    f.y = __uint_as_float((unsigned int)(u >> 32));
    return f;
}
__device__ __forceinline__ float gru1(float rv, float zv, float inv_, float hnv, float hold) {
    float r = 1.f / (1.f + __expf(-rv));
    float z = 1.f / (1.f + __expf(-zv));
    float n = tanhf(inv_ + r * hnv);
    return (1.f - z) * n + z * hold;
}

// ---------------- init / edge bucketing ----------------
__global__ void k_init() {
    int i = blockIdx.x * blockDim.x + threadIdx.x;
    if (i < TT) { d_counts[i] = 0; d_cursor[i] = 0; }
    if (i < NG) d_cnt[i] = 0.f;
    if (i < NG * D) d_pool[i] = 0.f;
}

__global__ void k_zeroS() {
    size_t i = (size_t)blockIdx.x * blockDim.x + threadIdx.x;
    size_t total = (size_t)TT * N_NODES * D / 4;
    float4 z = make_float4(0.f, 0.f, 0.f, 0.f);
    for (; i < total; i += (size_t)gridDim.x * blockDim.x)
        ((float4*)d_S)[i] = z;
}

__global__ void k_count(const int* __restrict__ eattr) {
    int e = blockIdx.x * blockDim.x + threadIdx.x;
    if (e < N_EDGES) atomicAdd(&d_counts[eattr[e]], 1);
}

__global__ void k_scan() {
    if (threadIdx.x == 0) {
        int a = 0;
        for (int t = 0; t < TT; t++) { d_offsets[t] = a; a += d_counts[t]; }
        d_offsets[TT] = a;
    }
}

__global__ void k_fill(const int* __restrict__ eidx,
                       const int* __restrict__ eattr) {
    int e = blockIdx.x * blockDim.x + threadIdx.x;
    if (e >= N_EDGES) return;
    int t = eattr[e];
    int p = atomicAdd(&d_cursor[t], 1);
    int idx = d_offsets[t] + p;
    d_esrc[idx] = t * N_NODES + eidx[e];
    d_edst[idx] = t * N_NODES + eidx[N_EDGES + e];
}

// ---------------- h0 = x @ lin_w + lin_b, broadcast to all 13 type slices ----------------
__global__ void k_h0(const float* __restrict__ x,
                     const float* __restrict__ lw,
                     const float* __restrict__ lb) {
    __shared__ float Ash[64][17];
    __shared__ float Bsh[16][128];
    const int m0 = blockIdx.x * 64;
    const int tid = threadIdx.x;
    const int tj = tid & 31;   // cols tj*4..tj*4+3
    const int tr = tid >> 5;   // row groups of 8

    float acc[8][4];
#pragma unroll
    for (int i = 0; i < 8; i++)
#pragma unroll
        for (int j = 0; j < 4; j++) acc[i][j] = 0.f;

    for (int c0 = 0; c0 < DIN; c0 += 16) {
#pragma unroll
        for (int i = 0; i < 4; i++) {
            int id = tid + i * 256;
            int r = id >> 4, c = id & 15;
            int gm = m0 + r, gc = c0 + c;
            Ash[r][c] = (gm < N_NODES && gc < DIN) ? x[(size_t)gm * DIN + gc] : 0.f;
        }
#pragma unroll
        for (int i = 0; i < 8; i++) {
            int id = tid + i * 256;
            int r = id >> 7, c = id & 127;
            int gc = c0 + r;
            Bsh[r][c] = (gc < DIN) ? lw[(size_t)gc * D + c] : 0.f;
        }
        __syncthreads();
#pragma unroll
        for (int k = 0; k < 16; k++) {
            float4 b = *(const float4*)&Bsh[k][tj * 4];
#pragma unroll
            for (int i = 0; i < 8; i++) {
                float a = Ash[tr * 8 + i][k];
                acc[i][0] += a * b.x; acc[i][1] += a * b.y;
                acc[i][2] += a * b.z; acc[i][3] += a * b.w;
            }
        }
        __syncthreads();
    }
    float4 lb4 = *(const float4*)&lb[tj * 4];
#pragma unroll
    for (int i = 0; i < 8; i++) {
        int gm = m0 + tr * 8 + i;
        if (gm >= N_NODES) continue;
        float4 v = make_float4(acc[i][0] + lb4.x, acc[i][1] + lb4.y,
                               acc[i][2] + lb4.z, acc[i][3] + lb4.w);
        size_t off = (size_t)gm * D + tj * 4;
        for (int t = 0; t < TT; t++)
            *(float4*)&d_H[(size_t)t * N_NODES * D + off] = v;
    }
}

// ---------------- Q[t,s] = W[t,s] @ w_ih[t]^T  (128x384, K=128) ----------------
__global__ void k_q(const float* __restrict__ W, const float* __restrict__ wih) {
    int ts = blockIdx.z;
    int t = ts >> 3;
    int m0 = blockIdx.x * 64;   // rows of Q (k index)
    int n0 = blockIdx.y * 64;   // cols of Q (j index)
    const float* A = W + (size_t)ts * D * D;
    const float* B = wih + (size_t)t * D3 * D;
    __shared__ float Ash[64][17];
    __shared__ float Bsh[16][65];
    const int tid = threadIdx.x;
    const int tj = tid & 15;
    const int tr = tid >> 4;
    float acc[4][4];
#pragma unroll
    for (int i = 0; i < 4; i++)
#pragma unroll
        for (int j = 0; j < 4; j++) acc[i][j] = 0.f;

    for (int c0 = 0; c0 < D; c0 += 16) {
#pragma unroll
        for (int i = 0; i < 4; i++) {
            int id = tid + i * 256;
            int r = id >> 4, c = id & 15;
            Ash[r][c] = A[(size_t)(m0 + r) * D + c0 + c];
        }
#pragma unroll
        for (int i = 0; i < 4; i++) {
            int id = tid + i * 256;
            int j = id >> 4, c = id & 15;
            Bsh[c][j] = B[(size_t)(n0 + j) * D + c0 + c];
        }
        __syncthreads();
#pragma unroll
        for (int k = 0; k < 16; k++) {
            float a[4], b[4];
#pragma unroll
            for (int i = 0; i < 4; i++) a[i] = Ash[tr * 4 + i][k];
#pragma unroll
            for (int j = 0; j < 4; j++) b[j] = Bsh[k][tj * 4 + j];
#pragma unroll
            for (int i = 0; i < 4; i++)
#pragma unroll
                for (int j = 0; j < 4; j++) acc[i][j] += a[i] * b[j];
        }
        __syncthreads();
    }
    float* Qo = d_Q + (size_t)ts * D * D3;
#pragma unroll
    for (int i = 0; i < 4; i++)
#pragma unroll
        for (int j = 0; j < 4; j++)
            Qo[(size_t)(m0 + tr * 4 + i) * D3 + n0 + tj * 4 + j] = acc[i][j];
}

// ---------------- R[t][k][j] = w_hh[t][j][k] ----------------
__global__ void k_r(const float* __restrict__ whh) {
    int i = blockIdx.x * blockDim.x + threadIdx.x;
    if (i >= TT * D * D3) return;
    int t = i / (D * D3);
    int rem = i - t * (D * D3);
    int k = rem / D3;
    int j = rem - k * D3;
    d_R[i] = whh[(size_t)t * D3 * D + (size_t)j * D + k];
}

// ---------------- scatter: S[t][dst] += H[t][src] over bucketed edges ----------------
__global__ void k_scatter() {
    int w = (blockIdx.x * blockDim.x + threadIdx.x) >> 5;
    int lane = threadIdx.x & 31;
    if (w >= N_EDGES) return;
    int so = d_esrc[w];
    int dd = d_edst[w];
    float4 v = ((const float4*)(d_H + (size_t)so * D))[lane];
    float* p = d_S + (size_t)dd * D + lane * 4;
    atomicAdd(p + 0, v.x);
    atomicAdd(p + 1, v.y);
    atomicAdd(p + 2, v.z);
    atomicAdd(p + 3, v.w);
}

// ---------------- fused [S@Q | h@R] + GRU gates, packed f32x2 FMA ----------------
// Epilogue also zeroes the consumed S tile, so no memset between steps.
#define GBK 8
__global__ void __launch_bounds__(256, 2) k_gates(int s,
                                                  const float* __restrict__ b_ih,
                                                  const float* __restrict__ b_hh) {
    const int t = blockIdx.y;
    const int m0 = blockIdx.x * 32;
    const float* __restrict__ Qp = d_Q + (size_t)(t * STEPS + s) * D * D3;
    const float* __restrict__ Rp = d_R + (size_t)t * D * D3;
    float* __restrict__ Hp = d_H + (size_t)t * N_NODES * D;
    float* __restrict__ Sp = d_S + (size_t)t * N_NODES * D;

    __shared__ unsigned long long Sd[GBK][36];   // duplicated (v,v) pairs, [k][row]
    __shared__ unsigned long long Hd[GBK][36];
    __shared__ float4 Qs[GBK * 96];              // [k][j/4], 12 KB
    __shared__ float4 Rs[GBK * 96];

    const int tid = threadIdx.x;
    const int tj = tid & 31;   // cols tj*4 .. tj*4+3
    const int tr = tid >> 5;   // row groups of 4

    // bias-initialized accumulators (r,z share gi+gh bias; n keeps them split)
    unsigned long long aR[4][2], aZ[4][2], aN[4][2], aH[4][2];
    {
        const float* bi = b_ih + t * D3;
        const float* bh = b_hh + t * D3;
        float vR[4], vZ[4], vN[4], vH[4];
#pragma unroll
        for (int j = 0; j < 4; j++) {
            int c = tj * 4 + j;
            vR[j] = bi[c] + bh[c];
            vZ[j] = bi[D + c] + bh[D + c];
            vN[j] = bi[2 * D + c];
            vH[j] = bh[2 * D + c];
        }
        unsigned long long pR0 = pack2(vR[0], vR[1]), pR1 = pack2(vR[2], vR[3]);
        unsigned long long pZ0 = pack2(vZ[0], vZ[1]), pZ1 = pack2(vZ[2], vZ[3]);
        unsigned long long pN0 = pack2(vN[0], vN[1]), pN1 = pack2(vN[2], vN[3]);
        unsigned long long pH0 = pack2(vH[0], vH[1]), pH1 = pack2(vH[2], vH[3]);
#pragma unroll
        for (int i = 0; i < 4; i++) {
            aR[i][0] = pR0; aR[i][1] = pR1;
            aZ[i][0] = pZ0; aZ[i][1] = pZ1;
            aN[i][0] = pN0; aN[i][1] = pN1;
            aH[i][0] = pH0; aH[i][1] = pH1;
        }
    }

    const int ldr = tid >> 3, ldc = tid & 7;
    for (int c0 = 0; c0 < D; c0 += GBK) {
        {
            int gm = m0 + ldr;
            float sv = 0.f, hv = 0.f;
            if (gm < N_NODES) {
                sv = Sp[(size_t)gm * D + c0 + ldc];
                hv = Hp[(size_t)gm * D + c0 + ldc];
            }
            Sd[ldc][ldr] = dup2(sv);
            Hd[ldc][ldr] = dup2(hv);
        }
        {
            const float4* Qg = (const float4*)(Qp + (size_t)c0 * D3);
            const float4* Rg = (const float4*)(Rp + (size_t)c0 * D3);
#pragma unroll
            for (int i = 0; i < 3; i++) {
                int id = tid + i * 256;
                Qs[id] = Qg[id];
                Rs[id] = Rg[id];
            }
        }
        __syncthreads();
#pragma unroll
        for (int k = 0; k < GBK; k++) {
            ulonglong2 qr = *(const ulonglong2*)&Qs[k * 96 + tj];
            ulonglong2 qz = *(const ulonglong2*)&Qs[k * 96 + 32 + tj];
            ulonglong2 qn = *(const ulonglong2*)&Qs[k * 96 + 64 + tj];
            ulonglong2 rr = *(const ulonglong2*)&Rs[k * 96 + tj];
            ulonglong2 rz = *(const ulonglong2*)&Rs[k * 96 + 32 + tj];
            ulonglong2 rn = *(const ulonglong2*)&Rs[k * 96 + 64 + tj];
#pragma unroll
            for (int i = 0; i < 4; i++) {
                unsigned long long sp = Sd[k][tr * 4 + i];
                unsigned long long hp = Hd[k][tr * 4 + i];
                fma2(aR[i][0], sp, qr.x); fma2(aR[i][0], hp, rr.x);
                fma2(aR[i][1], sp, qr.y); fma2(aR[i][1], hp, rr.y);
                fma2(aZ[i][0], sp, qz.x); fma2(aZ[i][0], hp, rz.x);
                fma2(aZ[i][1], sp, qz.y); fma2(aZ[i][1], hp, rz.y);
                fma2(aN[i][0], sp, qn.x); fma2(aN[i][1], sp, qn.y);
                fma2(aH[i][0], hp, rn.x); fma2(aH[i][1], hp, rn.y);
            }
        }
        __syncthreads();
    }

#pragma unroll
    for (int i = 0; i < 4; i++) {
        int gm = m0 + tr * 4 + i;
        if (gm >= N_NODES) continue;
        float* hp = Hp + (size_t)gm * D + tj * 4;
        float4 hold = *(const float4*)hp;
        float2 r0 = u2f2(aR[i][0]), r1 = u2f2(aR[i][1]);
        float2 z0 = u2f2(aZ[i][0]), z1 = u2f2(aZ[i][1]);
        float2 n0 = u2f2(aN[i][0]), n1 = u2f2(aN[i][1]);
        float2 g0 = u2f2(aH[i][0]), g1 = u2f2(aH[i][1]);
        float4 o;
        o.x = gru1(r0.x, z0.x, n0.x, g0.x, hold.x);
        o.y = gru1(r0.y, z0.y, n0.y, g0.y, hold.y);
        o.z = gru1(r1.x, z1.x, n1.x, g1.x, hold.z);
        o.w = gru1(r1.y, z1.y, n1.y, g1.y, hold.w);
        *(float4*)hp = o;
    }

    // zero the consumed S tile for the next step (replaces memset)
    {
        int zr = tid >> 3;               // 0..31 row within tile
        int zc = (tid & 7) * 16;         // 0,16,...,112
        int gm = m0 + zr;
        if (gm < N_NODES) {
            float4 z = make_float4(0.f, 0.f, 0.f, 0.f);
            float4* zp = (float4*)(Sp + (size_t)gm * D + zc);
            zp[0] = z; zp[1] = z; zp[2] = z; zp[3] = z;
        }
    }
}

// ---------------- pooling: pool[batch[n]] += sum_t H[t][n]; cnt[g] += 1 ----------------
__global__ void k_pool(const int* __restrict__ batch) {
    int w = (blockIdx.x * blockDim.x + threadIdx.x) >> 5;
    int lane = threadIdx.x & 31;
    if (w >= N_NODES) return;
    int g = batch[w];
    float4 acc = make_float4(0.f, 0.f, 0.f, 0.f);
    for (int t = 0; t < TT; t++) {
        float4 v = ((const float4*)(d_H + ((size_t)t * N_NODES + w) * D))[lane];
        acc.x += v.x; acc.y += v.y; acc.z += v.z; acc.w += v.w;
    }
    float* p = d_pool + (size_t)g * D + lane * 4;
    atomicAdd(p + 0, acc.x);
    atomicAdd(p + 1, acc.y);
    atomicAdd(p + 2, acc.z);
    atomicAdd(p + 3, acc.w);
    if (lane == 0) atomicAdd(&d_cnt[g], 1.f);
}

// ---------------- out[g] = (pool[g]/max(cnt,1)) @ cls_w + cls_b ----------------
__global__ void k_out(const float* __restrict__ cw, const float* __restrict__ cb,
                      float* __restrict__ out) {
    int g = blockIdx.x;
    int c = threadIdx.y;
    int lane = threadIdx.x;
    float inv = 1.f / fmaxf(d_cnt[g], 1.f);
    float acc = 0.f;
    for (int j = lane; j < D; j += 32)
        acc += d_pool[(size_t)g * D + j] * inv * cw[j * 2 + c];
#pragma unroll
    for (int o = 16; o; o >>= 1) acc += __shfl_down_sync(0xffffffffu, acc, o);
    if (lane == 0) out[g * 2 + c] = acc + cb[c];
}

// ---------------- launch ----------------
extern "C" void kernel_launch(void* const* d_in, const int* in_sizes, int n_in,
                              void* d_out, int out_size) {
    const float* x      = (const float*)d_in[0];
    const int*   eidx   = (const int*)d_in[1];     // int32 (JAX x64 disabled)
    const int*   eattr  = (const int*)d_in[2];     // int32
    const int*   batch  = (const int*)d_in[3];     // int32
    const float* lin_w  = (const float*)d_in[4];
    const float* lin_b  = (const float*)d_in[5];
    const float* ggnn_w = (const float*)d_in[6];
    const float* w_ih   = (const float*)d_in[7];
    const float* w_hh   = (const float*)d_in[8];
    const float* b_ih   = (const float*)d_in[9];
    const float* b_hh   = (const float*)d_in[10];
    const float* cls_w  = (const float*)d_in[11];
    const float* cls_b  = (const float*)d_in[12];
    float* out = (float*)d_out;
    (void)in_sizes; (void)n_in; (void)out_size;

    k_init<<<(NG * D + 255) / 256, 256>>>();
    k_zeroS<<<2048, 256>>>();
    k_count<<<(N_EDGES + 255) / 256, 256>>>(eattr);
    k_scan<<<1, 32>>>();
    k_fill<<<(N_EDGES + 255) / 256, 256>>>(eidx, eattr);
    k_h0<<<(N_NODES + 63) / 64, 256>>>(x, lin_w, lin_b);
    {
        dim3 g(2, 6, TT * STEPS);
        k_q<<<g, 256>>>(ggnn_w, w_ih);
    }
    k_r<<<(TT * D * D3 + 255) / 256, 256>>>(w_hh);

    for (int s = 0; s < STEPS; s++) {
        k_scatter<<<(N_EDGES * 32 + 255) / 256, 256>>>();
        dim3 gg((N_NODES + 31) / 32, TT);
        k_gates<<<gg, 256>>>(s, b_ih, b_hh);
    }
    k_pool<<<(N_NODES * 32 + 255) / 256, 256>>>(batch);
    k_out<<<NG, dim3(32, 2)>>>(cls_w, cls_b, out);
}